// round 1
// baseline (speedup 1.0000x reference)
#include <cuda_runtime.h>
#include <cstddef>

// Shapes (fixed by the problem)
#define B 16
#define W 256
#define S 512
#define H 768
#define L 12
#define E 256
// V = 50002 (unused directly)

// hidden_states: [L, B, S, H] fp32, layer stride = B*S*H
#define LAYER_STRIDE ((size_t)B * S * H)

// Block = 256 threads per (b, w) word.
//   threads [0,64):    copy W_embed[word_indices[b,w]] (E=256 fp32 = 64 float4)
//   threads [64,256):  192 threads x float4 = 768 fp32 bert span-mean
__global__ __launch_bounds__(256, 8)
void bert_lexer_kernel(const int* __restrict__ word_indices,
                       const int* __restrict__ span_start,
                       const int* __restrict__ span_end,
                       const float* __restrict__ W_embed,
                       const float* __restrict__ hidden,
                       float* __restrict__ out)
{
    const int bw  = blockIdx.x;            // 0 .. B*W-1
    const int b   = bw >> 8;               // W = 256
    const int tid = threadIdx.x;

    float* orow = out + (size_t)bw * (E + H);

    if (tid < 64) {
        // ---- word embedding gather: 64 threads x float4 = 256 floats ----
        const int wi = word_indices[bw];
        const float4* src = reinterpret_cast<const float4*>(W_embed + (size_t)wi * E);
        reinterpret_cast<float4*>(orow)[tid] = src[tid];
    } else {
        // ---- bert span mean: 192 threads x float4 = 768 floats ----
        const int t  = tid - 64;           // 0 .. 191
        const int s0 = span_start[bw];
        const int s1 = span_end[bw];
        const float inv = 1.0f / (12.0f * (float)(s1 - s0));

        float4 acc = make_float4(0.f, 0.f, 0.f, 0.f);

        for (int s = s0; s < s1; ++s) {
            const float* p = hidden + ((size_t)b * S + (size_t)s) * H + (size_t)t * 4;
            #pragma unroll
            for (int l = 0; l < L; ++l) {
                float4 v = *reinterpret_cast<const float4*>(p + (size_t)l * LAYER_STRIDE);
                acc.x += v.x; acc.y += v.y; acc.z += v.z; acc.w += v.w;
            }
        }
        acc.x *= inv; acc.y *= inv; acc.z *= inv; acc.w *= inv;
        reinterpret_cast<float4*>(orow + E)[t] = acc;
    }
}

extern "C" void kernel_launch(void* const* d_in, const int* in_sizes, int n_in,
                              void* d_out, int out_size)
{
    const int*   word_indices = (const int*)  d_in[0];   // [B, W]
    const int*   span_start   = (const int*)  d_in[1];   // [B, W]
    const int*   span_end     = (const int*)  d_in[2];   // [B, W]
    const float* W_embed      = (const float*)d_in[3];   // [V, E]
    const float* hidden       = (const float*)d_in[4];   // [L, B, S, H]
    float*       out          = (float*)      d_out;     // [B, W, E+H]

    (void)in_sizes; (void)n_in; (void)out_size;

    bert_lexer_kernel<<<B * W, 256>>>(word_indices, span_start, span_end,
                                      W_embed, hidden, out);
}